// round 11
// baseline (speedup 1.0000x reference)
#include <cuda_runtime.h>
#include <cuda_bf16.h>
#include <math.h>
#include <stdint.h>

#define BB 4
#define LL 2048
#define DD 1024
#define HH 16
#define DHH 64

typedef __nv_bfloat16 bf16;

// ---------------- scratch (allocation-free device globals) ----------------
__device__ float g_xr[(size_t)8192 * 1024];    // tf32-rounded x
__device__ float g_wqr[(size_t)3072 * 1024];   // tf32-rounded w_qkv
__device__ float g_wpr[(size_t)1024 * 1024];   // tf32-rounded w_proj
__device__ float g_ctx[(size_t)8192 * 1024];   // fp32 ctx (tf32-rounded)
__device__ bf16 g_qh[(size_t)64 * 2048 * 64], g_ql[(size_t)64 * 2048 * 64];
__device__ bf16 g_kh[(size_t)64 * 2048 * 64], g_kl[(size_t)64 * 2048 * 64];
__device__ bf16 g_vh[(size_t)64 * 2048 * 64], g_vl[(size_t)64 * 2048 * 64];

// ---------------- PTX helpers ----------------
__device__ __forceinline__ uint32_t smem_u32(const void* p) {
    uint32_t a;
    asm("{ .reg .u64 t; cvta.to.shared.u64 t, %1; cvt.u32.u64 %0, t; }"
        : "=r"(a) : "l"(p));
    return a;
}
__device__ __forceinline__ void ldsm_x4(uint32_t* r, uint32_t addr) {
    asm volatile("ldmatrix.sync.aligned.m8n8.x4.shared.b16 {%0,%1,%2,%3}, [%4];"
                 : "=r"(r[0]), "=r"(r[1]), "=r"(r[2]), "=r"(r[3]) : "r"(addr));
}
__device__ __forceinline__ void ldsm_x4_t(uint32_t* r, uint32_t addr) {
    asm volatile("ldmatrix.sync.aligned.m8n8.x4.trans.shared.b16 {%0,%1,%2,%3}, [%4];"
                 : "=r"(r[0]), "=r"(r[1]), "=r"(r[2]), "=r"(r[3]) : "r"(addr));
}
__device__ __forceinline__ void mma_bf16(float* d, const uint32_t* a,
                                         const uint32_t* b) {
    asm volatile(
        "mma.sync.aligned.m16n8k16.row.col.f32.bf16.bf16.f32 "
        "{%0,%1,%2,%3}, {%4,%5,%6,%7}, {%8,%9}, {%0,%1,%2,%3};"
        : "+f"(d[0]), "+f"(d[1]), "+f"(d[2]), "+f"(d[3])
        : "r"(a[0]), "r"(a[1]), "r"(a[2]), "r"(a[3]), "r"(b[0]), "r"(b[1]));
}
__device__ __forceinline__ void mma_tf32(float* d, float a0, float a1,
                                         float a2, float a3, float b0, float b1) {
    asm volatile(
        "mma.sync.aligned.m16n8k8.row.col.f32.tf32.tf32.f32 "
        "{%0,%1,%2,%3}, {%4,%5,%6,%7}, {%8,%9}, {%0,%1,%2,%3};"
        : "+f"(d[0]), "+f"(d[1]), "+f"(d[2]), "+f"(d[3])
        : "r"(__float_as_uint(a0)), "r"(__float_as_uint(a1)),
          "r"(__float_as_uint(a2)), "r"(__float_as_uint(a3)),
          "r"(__float_as_uint(b0)), "r"(__float_as_uint(b1)));
}
#define CP_ASYNC16(dst, src) \
    asm volatile("cp.async.cg.shared.global [%0], [%1], 16;" \
                 :: "r"(dst), "l"(src) : "memory")
#define CP_COMMIT() asm volatile("cp.async.commit_group;" ::: "memory")
#define CP_WAIT0()  asm volatile("cp.async.wait_group 0;" ::: "memory")

__device__ __forceinline__ uint32_t pack_bf16x2(float a, float b) {
    __nv_bfloat162 t = __floats2bfloat162_rn(a, b);
    return *(uint32_t*)&t;
}
__device__ __forceinline__ void split_bf16(float v, bf16& h, bf16& l) {
    h = __float2bfloat16(v);
    l = __float2bfloat16(v - __bfloat162float(h));
}
__device__ __forceinline__ float tf32_rnd(float x) {
    uint32_t u;
    asm("cvt.rna.tf32.f32 %0, %1;" : "=r"(u) : "f"(x));
    return __uint_as_float(u);
}

// ---------------------------------------------------------------------------
// conv_rnd: fp32 -> tf32-rounded fp32, elementwise
// ---------------------------------------------------------------------------
__global__ void conv_rnd(const float* __restrict__ src, float* __restrict__ dst,
                         int n4)
{
    int i = blockIdx.x * blockDim.x + threadIdx.x;
    if (i >= n4) return;
    float4 v = ((const float4*)src)[i];
    v.x = tf32_rnd(v.x); v.y = tf32_rnd(v.y);
    v.z = tf32_rnd(v.z); v.w = tf32_rnd(v.w);
    ((float4*)dst)[i] = v;
}

// ---------------------------------------------------------------------------
// TF32 GEMM:  C[m,n] = sum_k A[m,k]*B[n,k], K=1024, single-pass tf32.
// CTA tile 128x128x32, 8 warps (2x4), warp 64x32, k8 MMA steps.
// Inputs pre-rounded to tf32. Register prefetch -> static smem (pitch 36 f32,
// conflict-free scalar LDS fragments).
// mode 0: scatter bf16 hi/lo into g_q/g_k/g_v (q scaled). mode 1: fp32 -> Cp.
// ---------------------------------------------------------------------------
#define TP 36  // fp32 smem pitch (144 B); bank stride 4 -> conflict-free

__global__ __launch_bounds__(256) void tf32_gemm(
    const float* __restrict__ Ag, const float* __restrict__ Bg,
    float* __restrict__ Cp, int ldc, int mode)
{
    __shared__ float As[128][TP], Bs[128][TP];

    const int tid  = threadIdx.x;
    const int wid  = tid >> 5;
    const int lane = tid & 31;
    const int m0   = blockIdx.y * 128;
    const int n0   = blockIdx.x * 128;
    const int wm   = (wid >> 2) * 64;   // 2 warps in m
    const int wn   = (wid & 3) * 32;    // 4 warps in n
    const int g    = lane >> 2;         // group id 0..7
    const int tg   = lane & 3;          // thread in group 0..3

    // load mapping: per matrix 1024 x 16B segments; idx = it*256+tid (it<4)
    // row = idx>>3 (0..127), seg = idx&7 (16B each; 32 floats per row)
    const int lrow = tid >> 3, lseg = tid & 7;

    float c[4][4][4] = {};   // [mt][nt][4]
    uint4 pa[4], pb[4];

    #pragma unroll
    for (int it = 0; it < 4; it++) {
        int row = lrow + it * 32;
        pa[it] = *(const uint4*)(Ag + (size_t)(m0 + row) * 1024 + lseg * 4);
        pb[it] = *(const uint4*)(Bg + (size_t)(n0 + row) * 1024 + lseg * 4);
    }

    for (int ch = 0; ch < 32; ch++) {
        #pragma unroll
        for (int it = 0; it < 4; it++) {
            int row = lrow + it * 32;
            *(uint4*)(&As[row][lseg * 4]) = pa[it];
            *(uint4*)(&Bs[row][lseg * 4]) = pb[it];
        }
        __syncthreads();

        if (ch + 1 < 32) {
            const int k0 = (ch + 1) * 32;
            #pragma unroll
            for (int it = 0; it < 4; it++) {
                int row = lrow + it * 32;
                pa[it] = *(const uint4*)(Ag + (size_t)(m0 + row) * 1024 + k0 + lseg * 4);
                pb[it] = *(const uint4*)(Bg + (size_t)(n0 + row) * 1024 + k0 + lseg * 4);
            }
        }

        #pragma unroll
        for (int ks = 0; ks < 4; ks++) {
            const int kc = ks * 8;

            // B fragments: loaded once, reused by both... all 4 nt
            float b[4][2];
            #pragma unroll
            for (int nt = 0; nt < 4; nt++) {
                int brow = wn + nt * 8 + g;
                b[nt][0] = Bs[brow][kc + tg];
                b[nt][1] = Bs[brow][kc + 4 + tg];
            }

            // A fragments: short live range (one mt at a time)
            #pragma unroll
            for (int mt = 0; mt < 4; mt++) {
                int arow = wm + mt * 16 + g;
                float a0 = As[arow][kc + tg];
                float a1 = As[arow + 8][kc + tg];
                float a2 = As[arow][kc + 4 + tg];
                float a3 = As[arow + 8][kc + 4 + tg];
                #pragma unroll
                for (int nt = 0; nt < 4; nt++)
                    mma_tf32(c[mt][nt], a0, a1, a2, a3, b[nt][0], b[nt][1]);
            }
        }
        __syncthreads();
    }

    const int erow = g;
    const int ecol = tg * 2;

    if (mode == 1) {
        #pragma unroll
        for (int mt = 0; mt < 4; mt++)
            #pragma unroll
            for (int nt = 0; nt < 4; nt++) {
                int row = m0 + wm + mt * 16 + erow;
                int col = n0 + wn + nt * 8 + ecol;
                *(float2*)&Cp[(size_t)row * ldc + col] =
                    make_float2(c[mt][nt][0], c[mt][nt][1]);
                *(float2*)&Cp[(size_t)(row + 8) * ldc + col] =
                    make_float2(c[mt][nt][2], c[mt][nt][3]);
            }
    } else {
        const int which = n0 >> 10;
        bf16* dsth = (which == 0) ? g_qh : (which == 1) ? g_kh : g_vh;
        bf16* dstl = (which == 0) ? g_ql : (which == 1) ? g_kl : g_vl;
        const float sc = (which == 0) ? 0.125f : 1.0f;
        #pragma unroll
        for (int mt = 0; mt < 4; mt++)
            #pragma unroll
            for (int nt = 0; nt < 4; nt++) {
                int col = (n0 & 1023) + wn + nt * 8 + ecol;
                int h = col >> 6, dh = col & 63;
                #pragma unroll
                for (int rr = 0; rr < 2; rr++) {
                    int row = m0 + wm + mt * 16 + erow + rr * 8;
                    int b_ = row >> 11, l = row & 2047;
                    size_t base = ((size_t)((b_ << 4) + h) * 2048 + l) * 64 + dh;
                    float v0 = c[mt][nt][rr * 2 + 0] * sc;
                    float v1 = c[mt][nt][rr * 2 + 1] * sc;
                    bf16 h0, l0, h1, l1;
                    split_bf16(v0, h0, l0);
                    split_bf16(v1, h1, l1);
                    *(__nv_bfloat162*)(dsth + base) = __nv_bfloat162(h0, h1);
                    *(__nv_bfloat162*)(dstl + base) = __nv_bfloat162(l0, l1);
                }
            }
    }
}

// ---------------------------------------------------------------------------
// Flash attention, HMMA 3-term bf16 (unchanged math); epilogue now writes
// fp32 g_ctx (tf32-rounded) for the tf32 proj GEMM.
// ---------------------------------------------------------------------------
#define FP 72
#define FQ (128 * FP * 2)
#define FMAT (64 * FP * 2)
#define FSTAGE (4 * FMAT)
#define FLASH_SMEM (2 * FQ + 2 * FSTAGE)

__global__ __launch_bounds__(256) void flash_hmma()
{
    extern __shared__ char smem[];
    const uint32_t sb = smem_u32(smem);
    const uint32_t sQh = sb, sQl = sb + FQ;
    const uint32_t sKV = sb + 2 * FQ;

    const int tid  = threadIdx.x;
    const int wid  = tid >> 5;
    const int lane = tid & 31;
    const int bh   = blockIdx.y;
    const int q0   = blockIdx.x * 128;
    const int b    = bh >> 4;
    const int h    = bh & 15;

    const bf16* kvg[4] = {g_kh + (size_t)bh * 2048 * 64, g_kl + (size_t)bh * 2048 * 64,
                          g_vh + (size_t)bh * 2048 * 64, g_vl + (size_t)bh * 2048 * 64};

    {
        const bf16* qh_g = g_qh + (size_t)bh * 2048 * 64;
        const bf16* ql_g = g_ql + (size_t)bh * 2048 * 64;
        #pragma unroll
        for (int it = 0; it < 4; it++) {
            int i = tid + it * 256;
            int r = i >> 3, part = i & 7;
            uint4 v = *(const uint4*)(qh_g + (size_t)(q0 + r) * 64 + part * 8);
            *(uint4*)(smem + r * (FP * 2) + part * 16) = v;
            uint4 w = *(const uint4*)(ql_g + (size_t)(q0 + r) * 64 + part * 8);
            *(uint4*)(smem + FQ + r * (FP * 2) + part * 16) = w;
        }
    }

    #pragma unroll
    for (int it = 0; it < 8; it++) {
        int i = tid + it * 256;
        int mat = i >> 9, r = (i >> 3) & 63, part = i & 7;
        const bf16* src = kvg[mat] + (size_t)r * 64 + part * 8;
        uint32_t dst = sKV + mat * FMAT + r * (FP * 2) + part * 16;
        CP_ASYNC16(dst, src);
    }
    CP_COMMIT();
    __syncthreads();

    uint32_t qh[4][4], ql[4][4];
    #pragma unroll
    for (int ks = 0; ks < 4; ks++) {
        uint32_t off = (uint32_t)(wid * 16 + (lane & 15)) * (FP * 2)
                     + ks * 32 + (lane >> 4) * 16;
        ldsm_x4(qh[ks], sQh + off);
        ldsm_x4(ql[ks], sQl + off);
    }

    float o[8][4] = {};
    float mrow[2] = {-1e30f, -1e30f};
    float lrow[2] = {0.f, 0.f};

    for (int kb = 0; kb < 32; kb++) {
        CP_WAIT0();
        __syncthreads();

        if (kb + 1 < 32) {
            const uint32_t stg = sKV + ((kb + 1) & 1) * FSTAGE;
            const int krow0 = (kb + 1) * 64;
            #pragma unroll
            for (int it = 0; it < 8; it++) {
                int i = tid + it * 256;
                int mat = i >> 9, r = (i >> 3) & 63, part = i & 7;
                const bf16* src = kvg[mat] + (size_t)(krow0 + r) * 64 + part * 8;
                uint32_t dst = stg + mat * FMAT + r * (FP * 2) + part * 16;
                CP_ASYNC16(dst, src);
            }
            CP_COMMIT();
        }

        const uint32_t stg = sKV + (kb & 1) * FSTAGE;
        const uint32_t sKh = stg, sKl = stg + FMAT;
        const uint32_t sVh = stg + 2 * FMAT, sVl = stg + 3 * FMAT;

        float s[8][4] = {};
        #pragma unroll
        for (int ks = 0; ks < 4; ks++) {
            const uint32_t kc = (uint32_t)(ks * 32 + (lane >> 4) * 16);
            #pragma unroll
            for (int p = 0; p < 4; p++) {
                uint32_t kh4[4], kl4[4];
                uint32_t off = (uint32_t)(p * 16 + (lane & 15)) * (FP * 2) + kc;
                ldsm_x4(kh4, sKh + off);
                ldsm_x4(kl4, sKl + off);
                uint32_t b0h[2] = {kh4[0], kh4[2]}, b1h[2] = {kh4[1], kh4[3]};
                uint32_t b0l[2] = {kl4[0], kl4[2]}, b1l[2] = {kl4[1], kl4[3]};
                mma_bf16(s[2 * p],     qh[ks], b0h);
                mma_bf16(s[2 * p],     qh[ks], b0l);
                mma_bf16(s[2 * p],     ql[ks], b0h);
                mma_bf16(s[2 * p + 1], qh[ks], b1h);
                mma_bf16(s[2 * p + 1], qh[ks], b1l);
                mma_bf16(s[2 * p + 1], ql[ks], b1h);
            }
        }

        #pragma unroll
        for (int rh = 0; rh < 2; rh++) {
            float mx = -1e30f;
            #pragma unroll
            for (int nt = 0; nt < 8; nt++)
                mx = fmaxf(mx, fmaxf(s[nt][2 * rh], s[nt][2 * rh + 1]));
            mx = fmaxf(mx, __shfl_xor_sync(0xffffffffu, mx, 1));
            mx = fmaxf(mx, __shfl_xor_sync(0xffffffffu, mx, 2));
            float mnew = fmaxf(mrow[rh], mx);
            float corr = __expf(mrow[rh] - mnew);
            mrow[rh] = mnew;
            float rs = 0.f;
            #pragma unroll
            for (int nt = 0; nt < 8; nt++) {
                float p0 = __expf(s[nt][2 * rh] - mnew);
                float p1 = __expf(s[nt][2 * rh + 1] - mnew);
                s[nt][2 * rh] = p0;
                s[nt][2 * rh + 1] = p1;
                rs += p0 + p1;
            }
            rs += __shfl_xor_sync(0xffffffffu, rs, 1);
            rs += __shfl_xor_sync(0xffffffffu, rs, 2);
            lrow[rh] = lrow[rh] * corr + rs;
            #pragma unroll
            for (int nt = 0; nt < 8; nt++) {
                o[nt][2 * rh]     *= corr;
                o[nt][2 * rh + 1] *= corr;
            }
        }

        uint32_t ph[4][4], pl[4][4];
        #pragma unroll
        for (int ks = 0; ks < 4; ks++) {
            #pragma unroll
            for (int half = 0; half < 2; half++) {
                const float* sv = s[2 * ks + half];
                #pragma unroll
                for (int rr = 0; rr < 2; rr++) {
                    float v0 = sv[2 * rr], v1 = sv[2 * rr + 1];
                    bf16 h0, l0, h1, l1;
                    split_bf16(v0, h0, l0);
                    split_bf16(v1, h1, l1);
                    ph[ks][half * 2 + rr] = pack_bf16x2(__bfloat162float(h0),
                                                        __bfloat162float(h1));
                    pl[ks][half * 2 + rr] = pack_bf16x2(__bfloat162float(l0),
                                                        __bfloat162float(l1));
                }
            }
        }

        #pragma unroll
        for (int ks = 0; ks < 4; ks++) {
            #pragma unroll
            for (int p = 0; p < 4; p++) {
                uint32_t vh4[4], vl4[4];
                uint32_t off = (uint32_t)(ks * 16 + (lane & 15)) * (FP * 2)
                             + p * 32 + (lane >> 4) * 16;
                ldsm_x4_t(vh4, sVh + off);
                ldsm_x4_t(vl4, sVl + off);
                uint32_t b0h[2] = {vh4[0], vh4[1]}, b1h[2] = {vh4[2], vh4[3]};
                uint32_t b0l[2] = {vl4[0], vl4[1]}, b1l[2] = {vl4[2], vl4[3]};
                mma_bf16(o[2 * p],     ph[ks], b0h);
                mma_bf16(o[2 * p],     ph[ks], b0l);
                mma_bf16(o[2 * p],     pl[ks], b0h);
                mma_bf16(o[2 * p + 1], ph[ks], b1h);
                mma_bf16(o[2 * p + 1], ph[ks], b1l);
                mma_bf16(o[2 * p + 1], pl[ks], b1h);
            }
        }
    }

    const int erow = lane >> 2;
    const int ecol = (lane & 3) * 2;
    #pragma unroll
    for (int rh = 0; rh < 2; rh++) {
        float inv = 1.f / lrow[rh];
        int row = q0 + wid * 16 + erow + rh * 8;
        size_t rbase = (size_t)(b * 2048 + row) * 1024 + h * 64;
        #pragma unroll
        for (int nt = 0; nt < 8; nt++) {
            float v0 = tf32_rnd(o[nt][2 * rh] * inv);
            float v1 = tf32_rnd(o[nt][2 * rh + 1] * inv);
            *(float2*)(g_ctx + rbase + nt * 8 + ecol) = make_float2(v0, v1);
        }
    }
}

// ---------------------------------------------------------------------------
extern "C" void kernel_launch(void* const* d_in, const int* in_sizes, int n_in,
                              void* d_out, int out_size)
{
    const float* x      = (const float*)d_in[0];
    const float* w_qkv  = (const float*)d_in[1];
    const float* w_proj = (const float*)d_in[2];
    float* out          = (float*)d_out;

    float *xr, *wqr, *wpr, *ctx;
    cudaGetSymbolAddress((void**)&xr, g_xr);
    cudaGetSymbolAddress((void**)&wqr, g_wqr);
    cudaGetSymbolAddress((void**)&wpr, g_wpr);
    cudaGetSymbolAddress((void**)&ctx, g_ctx);

    conv_rnd<<<(8192 * 1024 / 4 + 255) / 256, 256>>>(x, xr, 8192 * 1024 / 4);
    conv_rnd<<<(3072 * 1024 / 4 + 255) / 256, 256>>>(w_qkv, wqr, 3072 * 1024 / 4);
    conv_rnd<<<(1024 * 1024 / 4 + 255) / 256, 256>>>(w_proj, wpr, 1024 * 1024 / 4);

    cudaFuncSetAttribute(flash_hmma,
                         cudaFuncAttributeMaxDynamicSharedMemorySize, FLASH_SMEM);

    // QKV: M=8192, N=3072 -> grid (24, 64)
    tf32_gemm<<<dim3(24, 64), 256>>>(xr, wqr, nullptr, 0, 0);

    // flash: 16 q-tiles x 64 (b,h)
    flash_hmma<<<dim3(16, 64), 256, FLASH_SMEM>>>();

    // proj: M=8192, N=1024 -> grid (8, 64)
    tf32_gemm<<<dim3(8, 64), 256>>>(ctx, wpr, out, 1024, 1);
}

// round 12
// speedup vs baseline: 1.3358x; 1.3358x over previous
#include <cuda_runtime.h>
#include <cuda_bf16.h>
#include <math.h>
#include <stdint.h>

#define BB 4
#define LL 2048
#define DD 1024
#define HH 16
#define DHH 64

typedef __nv_bfloat16 bf16;

// ---------------- scratch (allocation-free device globals) ----------------
__device__ bf16 g_xh[(size_t)8192 * 1024], g_xl[(size_t)8192 * 1024];
__device__ bf16 g_wqh[(size_t)3072 * 1024], g_wql[(size_t)3072 * 1024];
__device__ bf16 g_wph[(size_t)1024 * 1024], g_wpl[(size_t)1024 * 1024];
__device__ bf16 g_qh[(size_t)64 * 2048 * 64], g_ql[(size_t)64 * 2048 * 64];
__device__ bf16 g_kh[(size_t)64 * 2048 * 64], g_kl[(size_t)64 * 2048 * 64];
__device__ bf16 g_vh[(size_t)64 * 2048 * 64], g_vl[(size_t)64 * 2048 * 64];
__device__ bf16 g_ctxh[(size_t)8192 * 1024], g_ctxl[(size_t)8192 * 1024];

// ---------------- PTX helpers ----------------
__device__ __forceinline__ uint32_t smem_u32(const void* p) {
    uint32_t a;
    asm("{ .reg .u64 t; cvta.to.shared.u64 t, %1; cvt.u32.u64 %0, t; }"
        : "=r"(a) : "l"(p));
    return a;
}
__device__ __forceinline__ void ldsm_x4(uint32_t* r, uint32_t addr) {
    asm volatile("ldmatrix.sync.aligned.m8n8.x4.shared.b16 {%0,%1,%2,%3}, [%4];"
                 : "=r"(r[0]), "=r"(r[1]), "=r"(r[2]), "=r"(r[3]) : "r"(addr));
}
__device__ __forceinline__ void ldsm_x4_t(uint32_t* r, uint32_t addr) {
    asm volatile("ldmatrix.sync.aligned.m8n8.x4.trans.shared.b16 {%0,%1,%2,%3}, [%4];"
                 : "=r"(r[0]), "=r"(r[1]), "=r"(r[2]), "=r"(r[3]) : "r"(addr));
}
__device__ __forceinline__ void mma_bf16(float* d, const uint32_t* a,
                                         const uint32_t* b) {
    asm volatile(
        "mma.sync.aligned.m16n8k16.row.col.f32.bf16.bf16.f32 "
        "{%0,%1,%2,%3}, {%4,%5,%6,%7}, {%8,%9}, {%0,%1,%2,%3};"
        : "+f"(d[0]), "+f"(d[1]), "+f"(d[2]), "+f"(d[3])
        : "r"(a[0]), "r"(a[1]), "r"(a[2]), "r"(a[3]), "r"(b[0]), "r"(b[1]));
}
#define CP_ASYNC16(dst, src) \
    asm volatile("cp.async.cg.shared.global [%0], [%1], 16;" \
                 :: "r"(dst), "l"(src) : "memory")
#define CP_COMMIT() asm volatile("cp.async.commit_group;" ::: "memory")
#define CP_WAIT0()  asm volatile("cp.async.wait_group 0;" ::: "memory")

__device__ __forceinline__ uint32_t pack_bf16x2(float a, float b) {
    __nv_bfloat162 t = __floats2bfloat162_rn(a, b);
    return *(uint32_t*)&t;
}
__device__ __forceinline__ void split_bf16(float v, bf16& h, bf16& l) {
    h = __float2bfloat16(v);
    l = __float2bfloat16(v - __bfloat162float(h));
}

// ---------------------------------------------------------------------------
// conv_split: fp32 -> (hi, lo) bf16, elementwise
// ---------------------------------------------------------------------------
__global__ void conv_split(const float* __restrict__ src, bf16* __restrict__ h,
                           bf16* __restrict__ l, int n4)
{
    int i = blockIdx.x * blockDim.x + threadIdx.x;
    if (i >= n4) return;
    float4 v = ((const float4*)src)[i];
    bf16 h0, l0, h1, l1, h2, l2, h3, l3;
    split_bf16(v.x, h0, l0); split_bf16(v.y, h1, l1);
    split_bf16(v.z, h2, l2); split_bf16(v.w, h3, l3);
    ((__nv_bfloat162*)h)[2 * i]     = __nv_bfloat162(h0, h1);
    ((__nv_bfloat162*)h)[2 * i + 1] = __nv_bfloat162(h2, h3);
    ((__nv_bfloat162*)l)[2 * i]     = __nv_bfloat162(l0, l1);
    ((__nv_bfloat162*)l)[2 * i + 1] = __nv_bfloat162(l2, l3);
}

// ---------------------------------------------------------------------------
// HMMA GEMM, tile 128x128x32, warp 64x32 (ratio 4), register prefetch,
// DOUBLE-BUFFERED smem => ONE __syncthreads per chunk (96 MMAs/warp/sync).
// mode 0: scatter bf16 hi/lo into g_q/g_k/g_v (q scaled). mode 1: fp32 -> Cp.
// ---------------------------------------------------------------------------
#define GP 40                      // smem pitch in bf16 elems (80 B)
#define GMAT (128 * GP * 2)        // 10240 B per matrix
#define GSTAGE (4 * GMAT)          // 40960 B per stage
#define GEMM_SMEM (2 * GSTAGE)     // 81920 B

__global__ __launch_bounds__(256) void hmma_gemm(
    const bf16* __restrict__ Ah_g, const bf16* __restrict__ Al_g,
    const bf16* __restrict__ Bh_g, const bf16* __restrict__ Bl_g,
    float* __restrict__ Cp, int ldc, int mode)
{
    extern __shared__ char smem[];
    const uint32_t sb = smem_u32(smem);

    const int tid  = threadIdx.x;
    const int wid  = tid >> 5;
    const int lane = tid & 31;
    const int m0   = blockIdx.y * 128;
    const int n0   = blockIdx.x * 128;
    const int wm   = (wid >> 2) * 64;   // 2 warps in m
    const int wn   = (wid & 3) * 32;    // 4 warps in n

    const bf16* mats[4] = {Ah_g, Al_g, Bh_g, Bl_g};

    // load mapping: per matrix 512 x 16B segments; idx = it*256+tid,
    // row = idx>>2 (0..127), part = idx&3 (64 data B + 16 pad per 80B row)
    const int lrow = tid >> 2, lpart = tid & 3;

    float c[4][4][4] = {};   // [mt][nt][4]
    uint4 pre[4][2];

    #pragma unroll
    for (int mat = 0; mat < 4; mat++)
        #pragma unroll
        for (int it = 0; it < 2; it++) {
            int row = lrow + (it << 6);
            int grow = (mat < 2) ? (m0 + row) : (n0 + row);
            pre[mat][it] = *(const uint4*)(mats[mat] + (size_t)grow * 1024 + lpart * 8);
        }

    for (int ch = 0; ch < 32; ch++) {
        const uint32_t stg = sb + (ch & 1) * GSTAGE;

        // store prefetched chunk into this chunk's buffer
        #pragma unroll
        for (int mat = 0; mat < 4; mat++)
            #pragma unroll
            for (int it = 0; it < 2; it++) {
                int row = lrow + (it << 6);
                *(uint4*)(smem + (ch & 1) * GSTAGE + mat * GMAT
                          + row * (GP * 2) + lpart * 16) = pre[mat][it];
            }
        __syncthreads();   // single barrier per chunk

        // prefetch next chunk (LDGs hidden under the MMA block)
        if (ch + 1 < 32) {
            const int k0 = (ch + 1) * 32;
            #pragma unroll
            for (int mat = 0; mat < 4; mat++)
                #pragma unroll
                for (int it = 0; it < 2; it++) {
                    int row = lrow + (it << 6);
                    int grow = (mat < 2) ? (m0 + row) : (n0 + row);
                    pre[mat][it] = *(const uint4*)(mats[mat] + (size_t)grow * 1024
                                                   + k0 + lpart * 8);
                }
        }

        const uint32_t sAh = stg, sAl = stg + GMAT;
        const uint32_t sBh = stg + 2 * GMAT, sBl = stg + 3 * GMAT;

        #pragma unroll
        for (int ks = 0; ks < 2; ks++) {
            const uint32_t kc = (uint32_t)(ks * 32 + (lane >> 4) * 16);
            uint32_t ah[4][4], al[4][4];
            #pragma unroll
            for (int mt = 0; mt < 4; mt++) {
                uint32_t off = (uint32_t)(wm + mt * 16 + (lane & 15)) * (GP * 2) + kc;
                ldsm_x4(ah[mt], sAh + off);
                ldsm_x4(al[mt], sAl + off);
            }
            uint32_t bh[4][2], bl[4][2];
            #pragma unroll
            for (int half = 0; half < 2; half++) {
                uint32_t r4h[4], r4l[4];
                uint32_t off = (uint32_t)(wn + half * 16 + (lane & 15)) * (GP * 2) + kc;
                ldsm_x4(r4h, sBh + off);
                ldsm_x4(r4l, sBl + off);
                bh[half * 2 + 0][0] = r4h[0]; bh[half * 2 + 0][1] = r4h[2];
                bh[half * 2 + 1][0] = r4h[1]; bh[half * 2 + 1][1] = r4h[3];
                bl[half * 2 + 0][0] = r4l[0]; bl[half * 2 + 0][1] = r4l[2];
                bl[half * 2 + 1][0] = r4l[1]; bl[half * 2 + 1][1] = r4l[3];
            }
            #pragma unroll
            for (int mt = 0; mt < 4; mt++)
                #pragma unroll
                for (int nt = 0; nt < 4; nt++) {
                    mma_bf16(c[mt][nt], ah[mt], bh[nt]);
                    mma_bf16(c[mt][nt], ah[mt], bl[nt]);
                    mma_bf16(c[mt][nt], al[mt], bh[nt]);
                }
        }
        // no trailing barrier: next chunk writes the other buffer, and the
        // barrier inside chunk ch+1 orders compute(ch) before store(ch+2).
    }

    const int erow = lane >> 2;
    const int ecol = (lane & 3) * 2;

    if (mode == 1) {
        #pragma unroll
        for (int mt = 0; mt < 4; mt++)
            #pragma unroll
            for (int nt = 0; nt < 4; nt++) {
                int row = m0 + wm + mt * 16 + erow;
                int col = n0 + wn + nt * 8 + ecol;
                *(float2*)&Cp[(size_t)row * ldc + col] =
                    make_float2(c[mt][nt][0], c[mt][nt][1]);
                *(float2*)&Cp[(size_t)(row + 8) * ldc + col] =
                    make_float2(c[mt][nt][2], c[mt][nt][3]);
            }
    } else {
        const int which = n0 >> 10;
        bf16* dsth = (which == 0) ? g_qh : (which == 1) ? g_kh : g_vh;
        bf16* dstl = (which == 0) ? g_ql : (which == 1) ? g_kl : g_vl;
        const float sc = (which == 0) ? 0.125f : 1.0f;
        #pragma unroll
        for (int mt = 0; mt < 4; mt++)
            #pragma unroll
            for (int nt = 0; nt < 4; nt++) {
                int col = (n0 & 1023) + wn + nt * 8 + ecol;
                int h = col >> 6, dh = col & 63;
                #pragma unroll
                for (int rr = 0; rr < 2; rr++) {
                    int row = m0 + wm + mt * 16 + erow + rr * 8;
                    int b = row >> 11, l = row & 2047;
                    size_t base = ((size_t)((b << 4) + h) * 2048 + l) * 64 + dh;
                    float v0 = c[mt][nt][rr * 2 + 0] * sc;
                    float v1 = c[mt][nt][rr * 2 + 1] * sc;
                    bf16 h0, l0, h1, l1;
                    split_bf16(v0, h0, l0);
                    split_bf16(v1, h1, l1);
                    *(__nv_bfloat162*)(dsth + base) = __nv_bfloat162(h0, h1);
                    *(__nv_bfloat162*)(dstl + base) = __nv_bfloat162(l0, l1);
                }
            }
    }
}

// ---------------------------------------------------------------------------
// Flash attention, HMMA (unchanged — ~95% of mma.sync ceiling).
// ---------------------------------------------------------------------------
#define FP 72
#define FQ (128 * FP * 2)
#define FMAT (64 * FP * 2)
#define FSTAGE (4 * FMAT)
#define FLASH_SMEM (2 * FQ + 2 * FSTAGE)

__global__ __launch_bounds__(256) void flash_hmma()
{
    extern __shared__ char smem[];
    const uint32_t sb = smem_u32(smem);
    const uint32_t sQh = sb, sQl = sb + FQ;
    const uint32_t sKV = sb + 2 * FQ;

    const int tid  = threadIdx.x;
    const int wid  = tid >> 5;
    const int lane = tid & 31;
    const int bh   = blockIdx.y;
    const int q0   = blockIdx.x * 128;
    const int b    = bh >> 4;
    const int h    = bh & 15;

    const bf16* kvg[4] = {g_kh + (size_t)bh * 2048 * 64, g_kl + (size_t)bh * 2048 * 64,
                          g_vh + (size_t)bh * 2048 * 64, g_vl + (size_t)bh * 2048 * 64};

    {
        const bf16* qh_g = g_qh + (size_t)bh * 2048 * 64;
        const bf16* ql_g = g_ql + (size_t)bh * 2048 * 64;
        #pragma unroll
        for (int it = 0; it < 4; it++) {
            int i = tid + it * 256;
            int r = i >> 3, part = i & 7;
            uint4 v = *(const uint4*)(qh_g + (size_t)(q0 + r) * 64 + part * 8);
            *(uint4*)(smem + r * (FP * 2) + part * 16) = v;
            uint4 w = *(const uint4*)(ql_g + (size_t)(q0 + r) * 64 + part * 8);
            *(uint4*)(smem + FQ + r * (FP * 2) + part * 16) = w;
        }
    }

    #pragma unroll
    for (int it = 0; it < 8; it++) {
        int i = tid + it * 256;
        int mat = i >> 9, r = (i >> 3) & 63, part = i & 7;
        const bf16* src = kvg[mat] + (size_t)r * 64 + part * 8;
        uint32_t dst = sKV + mat * FMAT + r * (FP * 2) + part * 16;
        CP_ASYNC16(dst, src);
    }
    CP_COMMIT();
    __syncthreads();

    uint32_t qh[4][4], ql[4][4];
    #pragma unroll
    for (int ks = 0; ks < 4; ks++) {
        uint32_t off = (uint32_t)(wid * 16 + (lane & 15)) * (FP * 2)
                     + ks * 32 + (lane >> 4) * 16;
        ldsm_x4(qh[ks], sQh + off);
        ldsm_x4(ql[ks], sQl + off);
    }

    float o[8][4] = {};
    float mrow[2] = {-1e30f, -1e30f};
    float lrow[2] = {0.f, 0.f};

    for (int kb = 0; kb < 32; kb++) {
        CP_WAIT0();
        __syncthreads();

        if (kb + 1 < 32) {
            const uint32_t stg = sKV + ((kb + 1) & 1) * FSTAGE;
            const int krow0 = (kb + 1) * 64;
            #pragma unroll
            for (int it = 0; it < 8; it++) {
                int i = tid + it * 256;
                int mat = i >> 9, r = (i >> 3) & 63, part = i & 7;
                const bf16* src = kvg[mat] + (size_t)(krow0 + r) * 64 + part * 8;
                uint32_t dst = stg + mat * FMAT + r * (FP * 2) + part * 16;
                CP_ASYNC16(dst, src);
            }
            CP_COMMIT();
        }

        const uint32_t stg = sKV + (kb & 1) * FSTAGE;
        const uint32_t sKh = stg, sKl = stg + FMAT;
        const uint32_t sVh = stg + 2 * FMAT, sVl = stg + 3 * FMAT;

        float s[8][4] = {};
        #pragma unroll
        for (int ks = 0; ks < 4; ks++) {
            const uint32_t kc = (uint32_t)(ks * 32 + (lane >> 4) * 16);
            #pragma unroll
            for (int p = 0; p < 4; p++) {
                uint32_t kh4[4], kl4[4];
                uint32_t off = (uint32_t)(p * 16 + (lane & 15)) * (FP * 2) + kc;
                ldsm_x4(kh4, sKh + off);
                ldsm_x4(kl4, sKl + off);
                uint32_t b0h[2] = {kh4[0], kh4[2]}, b1h[2] = {kh4[1], kh4[3]};
                uint32_t b0l[2] = {kl4[0], kl4[2]}, b1l[2] = {kl4[1], kl4[3]};
                mma_bf16(s[2 * p],     qh[ks], b0h);
                mma_bf16(s[2 * p],     qh[ks], b0l);
                mma_bf16(s[2 * p],     ql[ks], b0h);
                mma_bf16(s[2 * p + 1], qh[ks], b1h);
                mma_bf16(s[2 * p + 1], qh[ks], b1l);
                mma_bf16(s[2 * p + 1], ql[ks], b1h);
            }
        }

        #pragma unroll
        for (int rh = 0; rh < 2; rh++) {
            float mx = -1e30f;
            #pragma unroll
            for (int nt = 0; nt < 8; nt++)
                mx = fmaxf(mx, fmaxf(s[nt][2 * rh], s[nt][2 * rh + 1]));
            mx = fmaxf(mx, __shfl_xor_sync(0xffffffffu, mx, 1));
            mx = fmaxf(mx, __shfl_xor_sync(0xffffffffu, mx, 2));
            float mnew = fmaxf(mrow[rh], mx);
            float corr = __expf(mrow[rh] - mnew);
            mrow[rh] = mnew;
            float rs = 0.f;
            #pragma unroll
            for (int nt = 0; nt < 8; nt++) {
                float p0 = __expf(s[nt][2 * rh] - mnew);
                float p1 = __expf(s[nt][2 * rh + 1] - mnew);
                s[nt][2 * rh] = p0;
                s[nt][2 * rh + 1] = p1;
                rs += p0 + p1;
            }
            rs += __shfl_xor_sync(0xffffffffu, rs, 1);
            rs += __shfl_xor_sync(0xffffffffu, rs, 2);
            lrow[rh] = lrow[rh] * corr + rs;
            #pragma unroll
            for (int nt = 0; nt < 8; nt++) {
                o[nt][2 * rh]     *= corr;
                o[nt][2 * rh + 1] *= corr;
            }
        }

        uint32_t ph[4][4], pl[4][4];
        #pragma unroll
        for (int ks = 0; ks < 4; ks++) {
            #pragma unroll
            for (int half = 0; half < 2; half++) {
                const float* sv = s[2 * ks + half];
                #pragma unroll
                for (int rr = 0; rr < 2; rr++) {
                    float v0 = sv[2 * rr], v1 = sv[2 * rr + 1];
                    bf16 h0, l0, h1, l1;
                    split_bf16(v0, h0, l0);
                    split_bf16(v1, h1, l1);
                    ph[ks][half * 2 + rr] = pack_bf16x2(__bfloat162float(h0),
                                                        __bfloat162float(h1));
                    pl[ks][half * 2 + rr] = pack_bf16x2(__bfloat162float(l0),
                                                        __bfloat162float(l1));
                }
            }
        }

        #pragma unroll
        for (int ks = 0; ks < 4; ks++) {
            #pragma unroll
            for (int p = 0; p < 4; p++) {
                uint32_t vh4[4], vl4[4];
                uint32_t off = (uint32_t)(ks * 16 + (lane & 15)) * (FP * 2)
                             + p * 32 + (lane >> 4) * 16;
                ldsm_x4_t(vh4, sVh + off);
                ldsm_x4_t(vl4, sVl + off);
                uint32_t b0h[2] = {vh4[0], vh4[1]}, b1h[2] = {vh4[2], vh4[3]};
                uint32_t b0l[2] = {vl4[0], vl4[1]}, b1l[2] = {vl4[2], vl4[3]};
                mma_bf16(o[2 * p],     ph[ks], b0h);
                mma_bf16(o[2 * p],     ph[ks], b0l);
                mma_bf16(o[2 * p],     pl[ks], b0h);
                mma_bf16(o[2 * p + 1], ph[ks], b1h);
                mma_bf16(o[2 * p + 1], ph[ks], b1l);
                mma_bf16(o[2 * p + 1], pl[ks], b1h);
            }
        }
    }

    const int erow = lane >> 2;
    const int ecol = (lane & 3) * 2;
    #pragma unroll
    for (int rh = 0; rh < 2; rh++) {
        float inv = 1.f / lrow[rh];
        int row = q0 + wid * 16 + erow + rh * 8;
        size_t rbase = (size_t)(b * 2048 + row) * 1024 + h * 64;
        #pragma unroll
        for (int nt = 0; nt < 8; nt++) {
            float v0 = o[nt][2 * rh] * inv;
            float v1 = o[nt][2 * rh + 1] * inv;
            bf16 h0, l0, h1, l1;
            split_bf16(v0, h0, l0);
            split_bf16(v1, h1, l1);
            size_t idx = rbase + nt * 8 + ecol;
            *(__nv_bfloat162*)(g_ctxh + idx) = __nv_bfloat162(h0, h1);
            *(__nv_bfloat162*)(g_ctxl + idx) = __nv_bfloat162(l0, l1);
        }
    }
}

// ---------------------------------------------------------------------------
extern "C" void kernel_launch(void* const* d_in, const int* in_sizes, int n_in,
                              void* d_out, int out_size)
{
    const float* x      = (const float*)d_in[0];
    const float* w_qkv  = (const float*)d_in[1];
    const float* w_proj = (const float*)d_in[2];
    float* out          = (float*)d_out;

    bf16 *xh, *xl, *wqh, *wql, *wph, *wpl, *ctxh, *ctxl;
    cudaGetSymbolAddress((void**)&xh, g_xh);
    cudaGetSymbolAddress((void**)&xl, g_xl);
    cudaGetSymbolAddress((void**)&wqh, g_wqh);
    cudaGetSymbolAddress((void**)&wql, g_wql);
    cudaGetSymbolAddress((void**)&wph, g_wph);
    cudaGetSymbolAddress((void**)&wpl, g_wpl);
    cudaGetSymbolAddress((void**)&ctxh, g_ctxh);
    cudaGetSymbolAddress((void**)&ctxl, g_ctxl);

    conv_split<<<(8192 * 1024 / 4 + 255) / 256, 256>>>(x, xh, xl, 8192 * 1024 / 4);
    conv_split<<<(3072 * 1024 / 4 + 255) / 256, 256>>>(w_qkv, wqh, wql, 3072 * 1024 / 4);
    conv_split<<<(1024 * 1024 / 4 + 255) / 256, 256>>>(w_proj, wph, wpl, 1024 * 1024 / 4);

    cudaFuncSetAttribute(hmma_gemm,
                         cudaFuncAttributeMaxDynamicSharedMemorySize, GEMM_SMEM);
    cudaFuncSetAttribute(flash_hmma,
                         cudaFuncAttributeMaxDynamicSharedMemorySize, FLASH_SMEM);

    // QKV: M=8192, N=3072 -> grid (24, 64)
    hmma_gemm<<<dim3(24, 64), 256, GEMM_SMEM>>>(xh, xl, wqh, wql, nullptr, 0, 0);

    // flash: 16 q-tiles x 64 (b,h)
    flash_hmma<<<dim3(16, 64), 256, FLASH_SMEM>>>();

    // proj: M=8192, N=1024 -> grid (8, 64)
    hmma_gemm<<<dim3(8, 64), 256, GEMM_SMEM>>>(ctxh, ctxl, wph, wpl, out, 1024, 1);
}